// round 1
// baseline (speedup 1.0000x reference)
#include <cuda_runtime.h>
#include <math_constants.h>

// CRF loss: forward (log-partition) minus gold score, summed over batch.
// Scaled-forward algorithm: probability-domain matvec with exact power-of-2
// rescaling, so the per-step cost is ~50 FMA + 1 EX2 instead of 2500 exps.

constexpr int TT   = 50;    // number of tags
constexpr int LL   = 256;   // max sequence length
constexpr int NTH  = 64;    // threads per block (2 warps)
constexpr int STARTT = TT - 2;
constexpr int STOPT  = TT - 1;

#define LOG2E 1.4426950408889634f
#define LN2F  0.6931471805599453f

__device__ float g_partial[4096];

__device__ __forceinline__ float blockMax(float v, volatile float* red) {
#pragma unroll
    for (int o = 16; o; o >>= 1) v = fmaxf(v, __shfl_xor_sync(0xffffffffu, v, o));
    if ((threadIdx.x & 31) == 0) red[threadIdx.x >> 5] = v;
    __syncthreads();
    v = fmaxf(red[0], red[1]);
    __syncthreads();
    return v;
}

__device__ __forceinline__ float blockSum(float v, volatile float* red) {
#pragma unroll
    for (int o = 16; o; o >>= 1) v += __shfl_xor_sync(0xffffffffu, v, o);
    if ((threadIdx.x & 31) == 0) red[threadIdx.x >> 5] = v;
    __syncthreads();
    v = red[0] + red[1];
    __syncthreads();
    return v;
}

__global__ void __launch_bounds__(NTH)
crf_kernel(const float* __restrict__ feats, const float* __restrict__ trans,
           const int* __restrict__ tags, const int* __restrict__ mask) {
    __shared__ float4 Pbuf[2][16];   // ping-pong P vector (64 floats each, 16B aligned)
    __shared__ float red[2];

    const int b   = blockIdx.x;
    const int tid = threadIdx.x;
    const int j   = tid;

    // ---- sequence length (mask is monotone: arange < length) ----
    int lm = 0;
    for (int t = tid; t < LL; t += NTH) lm += mask[b * LL + t];
    const int len = (int)(blockSum((float)lm, red) + 0.5f);

    // ---- E[:,j] = exp(trans[:,j]) held in registers of thread j ----
    float Ecol[TT];
    if (j < TT) {
#pragma unroll
        for (int i = 0; i < TT; i++) Ecol[i] = exp2f(trans[i * TT + j] * LOG2E);
    } else {
#pragma unroll
        for (int i = 0; i < TT; i++) Ecol[i] = 0.f;
    }

    const float* fb = feats + (size_t)b * LL * TT;

    // ---- init: part0 = feats[:,0,:] + trans[START,:] ----
    float v0 = (j < TT) ? fb[j] + trans[STARTT * TT + j] : -CUDART_INF_F;
    float m0 = blockMax(v0, red);
    float C2 = m0 * LOG2E;                 // accumulated log2 scale
    {
        float* P0 = (float*)Pbuf[0];
        if (j < TT) P0[j] = exp2f((v0 - m0) * LOG2E);
    }
    __syncthreads();

    int cur = 0;
    float fnext = (j < TT && len > 1) ? fb[TT + j] : 0.f;

    for (int t = 1; t < len; ++t) {
        float fcur = fnext;
        if (t + 1 < len && j < TT) fnext = fb[(t + 1) * TT + j];  // prefetch

        // matvec: acc = sum_i P[i] * E[i][j]
        const float4* p4 = (const float4*)Pbuf[cur];
        float a0 = 0.f, a1 = 0.f, a2 = 0.f, a3 = 0.f;
#pragma unroll
        for (int q = 0; q < 12; q++) {
            float4 pv = p4[q];
            a0 += pv.x * Ecol[4 * q + 0];
            a1 += pv.y * Ecol[4 * q + 1];
            a2 += pv.z * Ecol[4 * q + 2];
            a3 += pv.w * Ecol[4 * q + 3];
        }
        const float* pc = (const float*)Pbuf[cur];
        a0 += pc[48] * Ecol[48];
        a1 += pc[49] * Ecol[49];
        float acc = (a0 + a1) + (a2 + a3);

        float qv = (j < TT) ? acc * exp2f(fcur * LOG2E) : 0.f;

        // exact power-of-2 rescale every 4 steps (no MUFU, exact C2 bookkeeping)
        if ((t & 3) == 0 || t == len - 1) {
            float m = blockMax(qv, red);
            int k = (__float_as_int(m) >> 23) - 127;
            qv *= __int_as_float((127 - k) << 23);
            C2 += (float)k;
        }

        float* pn = (float*)Pbuf[cur ^ 1];
        if (j < TT) pn[j] = qv;
        __syncthreads();
        cur ^= 1;
    }

    // ---- terminal: logsumexp_i(part[i] + trans[i, STOP]) ----
    float tcol = (tid < TT) ? trans[tid * TT + STOPT] : -CUDART_INF_F;
    float mt = blockMax(tcol, red);
    const float* pc = (const float*)Pbuf[cur];
    float pv = (tid < TT) ? pc[tid] * exp2f((tcol - mt) * LOG2E) : 0.f;
    float sumv = blockSum(pv, red);
    float fwd = (C2 + log2f(sumv)) * LN2F + mt;

    // ---- gold score ----
    float gl = 0.f;
    const int* tgb = tags + b * LL;
    for (int t = tid; t < len; t += NTH) {
        int tg  = tgb[t];
        int pvt = (t == 0) ? STARTT : tgb[t - 1];
        gl += fb[t * TT + tg] + trans[pvt * TT + tg];
    }
    float gold = blockSum(gl, red);

    if (tid == 0) {
        gold += trans[tgb[len - 1] * TT + STOPT];
        g_partial[b] = fwd - gold;
    }
}

__global__ void crf_finalize(float* __restrict__ out, int B) {
    if (threadIdx.x == 0) {
        float s = 0.f;
        for (int i = 0; i < B; i++) s += g_partial[i];
        *out = s;
    }
}

extern "C" void kernel_launch(void* const* d_in, const int* in_sizes, int n_in,
                              void* d_out, int out_size) {
    const float* feats = (const float*)d_in[0];
    const float* trans = (const float*)d_in[1];
    const int*   tags  = (const int*)d_in[2];
    const int*   mask  = (const int*)d_in[3];
    int B = in_sizes[0] / (LL * TT);

    crf_kernel<<<B, NTH>>>(feats, trans, tags, mask);
    crf_finalize<<<1, 32>>>((float*)d_out, B);
}